// round 11
// baseline (speedup 1.0000x reference)
#include <cuda_runtime.h>

#define NN 500000
#define EE 8000000
#define BN_EPS 1e-5

// ---------------- scratch (static device memory; no allocation) ----------------
//  [0:2N)   aggUI  (float2: aggU, indeg)   [zeroed in k_init]
//  [2N:4N)  aggVM  (float2: aggV, aggM)    [zeroed in k_node1]
//  [4N:5N)  aggP                            [zeroed in k_node2]
//  [6N:8N)  uk     (float2: u, k)
//  [8N:9N)  v
//  [9N:10N) m
//  [10N:11N) p
__device__ float g_scratch[11 * NN];
__device__ int4 g_src[EE / 4];   // packed int32 src (only used when input is int64)
__device__ int4 g_dst[EE / 4];   // packed int32 dst
__device__ int g_is32;

struct Stats {
    double two_m;
    double Su, Suu, Sk, Skk;
    double Sv, Svv, Svk;
    double Sm, Smm, Smk;
    double Sp, Spp, Spm, Spk;
    double pos;
    double ds[4];
};
__device__ Stats g_stats;

struct Coef {
    float Lu[4], Lv[4], Lk[4], Lp[4], Lm[4], L0[4];
    float ubar, vbar, kbar, pbar, mbar;
};
__device__ Coef g_coef;

__device__ __forceinline__ float warp_redf(float v) {
#pragma unroll
    for (int o = 16; o > 0; o >>= 1) v += __shfl_down_sync(0xffffffffu, v, o);
    return v;
}

// Block-level reduction of NV float partials -> ONE double atomic per block per value.
template <int NV>
__device__ __forceinline__ void block_red_atomic(const float* vals, double* const* dsts) {
    __shared__ float sm[NV][8];
    int wid = threadIdx.x >> 5, lid = threadIdx.x & 31;
#pragma unroll
    for (int j = 0; j < NV; j++) {
        float v = warp_redf(vals[j]);
        if (lid == 0) sm[j][wid] = v;
    }
    __syncthreads();
    if (threadIdx.x < NV) {
        float t = 0.0f;
#pragma unroll
        for (int r = 0; r < 8; r++) t += sm[threadIdx.x][r];
        atomicAdd(dsts[threadIdx.x], (double)t);
    }
}

// vector reduction: one 8B atomic add of {a,b} (sm_90+)
__device__ __forceinline__ void red_add_v2(float2* addr, float a, float b) {
    asm volatile("red.global.add.v2.f32 [%0], {%1, %2};"
                 :: "l"(addr), "f"(a), "f"(b) : "memory");
}

__device__ __forceinline__ const int4* srcp(const void* ei, int is32) {
    return is32 ? reinterpret_cast<const int4*>(ei) : g_src;
}
__device__ __forceinline__ const int4* dstp(const void* ei, int is32) {
    return is32 ? reinterpret_cast<const int4*>((const int*)ei + EE) : g_dst;
}

// ---------------- init: zero aggUI + stats, detect index dtype ----------------
__global__ void k_init(const void* ei) {
    int stride = gridDim.x * blockDim.x;
    int tid = blockIdx.x * blockDim.x + threadIdx.x;
    float4* z4 = reinterpret_cast<float4*>(g_scratch);
    const int nz = (2 * NN) / 4;           // aggUI only
    for (int i = tid; i < nz; i += stride) z4[i] = make_float4(0.f, 0.f, 0.f, 0.f);
    if (tid < (int)(sizeof(Stats) / sizeof(double))) {
        reinterpret_cast<double*>(&g_stats)[tid] = 0.0;
    }
    if (blockIdx.x == 0) {
        const long long* p = (const long long*)ei;
        int bad = 0;
        for (int i = threadIdx.x; i < 4096; i += blockDim.x) {
            long long v = p[i];
            if (v < 0 || v >= (long long)NN) bad = 1;
        }
        bad = __syncthreads_or(bad);
        if (threadIdx.x == 0) g_is32 = bad;
    }
}

// ------- edge pass 1: aggUI[d] += {x[s],1} (v2 red); pack idx if int64 -------
__global__ void __launch_bounds__(256, 8) k_edge1(const void* __restrict__ ei,
                                                  const float* __restrict__ x) {
    float2* aggUI = reinterpret_cast<float2*>(g_scratch);
    const int is32 = g_is32;
    const int NQ = EE / 4;
    int stride = gridDim.x * blockDim.x;
    for (int q = blockIdx.x * blockDim.x + threadIdx.x; q < NQ; q += stride) {
        int4 S, D;
        if (is32) {
            S = __ldg(reinterpret_cast<const int4*>(ei) + q);
            D = __ldg(reinterpret_cast<const int4*>((const int*)ei + EE) + q);
        } else {
            const longlong2* p = reinterpret_cast<const longlong2*>(ei);
            longlong2 a0 = __ldg(p + 2 * q), a1 = __ldg(p + 2 * q + 1);
            longlong2 b0 = __ldg(p + EE / 2 + 2 * q), b1 = __ldg(p + EE / 2 + 2 * q + 1);
            S = make_int4((int)a0.x, (int)a0.y, (int)a1.x, (int)a1.y);
            D = make_int4((int)b0.x, (int)b0.y, (int)b1.x, (int)b1.y);
            g_src[q] = S;
            g_dst[q] = D;
        }
        float xs0 = __ldg(x + S.x);
        float xs1 = __ldg(x + S.y);
        float xs2 = __ldg(x + S.z);
        float xs3 = __ldg(x + S.w);
        red_add_v2(&aggUI[D.x], xs0, 1.0f);
        red_add_v2(&aggUI[D.y], xs1, 1.0f);
        red_add_v2(&aggUI[D.z], xs2, 1.0f);
        red_add_v2(&aggUI[D.w], xs3, 1.0f);
    }
}

// --- node pass 1: u = x + aggU, k = 1 + indeg, stats; also zero aggVM for edge2 ---
__global__ void k_node1(const float* __restrict__ x) {
    const float4* aggUI4 = reinterpret_cast<const float4*>(g_scratch);
    float4* aggVM4 = reinterpret_cast<float4*>(g_scratch + 2 * NN);
    float4* uk4 = reinterpret_cast<float4*>(g_scratch + 6 * NN);
    const float2* x2 = reinterpret_cast<const float2*>(x);
    float su = 0, suu = 0, sk = 0, skk = 0;
    int stride = gridDim.x * blockDim.x;
    const int NH = NN / 2;
    for (int i = blockIdx.x * blockDim.x + threadIdx.x; i < NH; i += stride) {
        float4 a = aggUI4[i];
        float2 xi = x2[i];
        float u0 = xi.x + a.x, k0 = 1.0f + a.y;
        float u1 = xi.y + a.z, k1 = 1.0f + a.w;
        uk4[i] = make_float4(u0, k0, u1, k1);
        aggVM4[i] = make_float4(0.f, 0.f, 0.f, 0.f);
        su += u0 + u1; suu += u0 * u0 + u1 * u1;
        sk += k0 + k1; skk += k0 * k0 + k1 * k1;
    }
    float vals[4] = {su, suu, sk, skk};
    double* dsts[4] = {&g_stats.Su, &g_stats.Suu, &g_stats.Sk, &g_stats.Skk};
    block_red_atomic<4>(vals, dsts);
}

// ---------------- edge pass 2: aggVM[d] += uk[s]  (one v2 red) ----------------
__global__ void __launch_bounds__(256, 8) k_edge2(const void* __restrict__ ei) {
    const float2* uk = reinterpret_cast<const float2*>(g_scratch + 6 * NN);
    float2* aggVM = reinterpret_cast<float2*>(g_scratch + 2 * NN);
    const int is32 = g_is32;
    const int4* sp = srcp(ei, is32);
    const int4* dp = dstp(ei, is32);
    const int NQ = EE / 4;
    int stride = gridDim.x * blockDim.x;
    for (int q = blockIdx.x * blockDim.x + threadIdx.x; q < NQ; q += stride) {
        int4 S = __ldg(sp + q);
        int4 D = __ldg(dp + q);
        float2 u0 = __ldg(&uk[S.x]);
        float2 u1 = __ldg(&uk[S.y]);
        float2 u2 = __ldg(&uk[S.z]);
        float2 u3 = __ldg(&uk[S.w]);
        red_add_v2(&aggVM[D.x], u0.x, u0.y);
        red_add_v2(&aggVM[D.y], u1.x, u1.y);
        red_add_v2(&aggVM[D.z], u2.x, u2.y);
        red_add_v2(&aggVM[D.w], u3.x, u3.y);
    }
}

// --- node pass 2: v = u + aggV, m = k + aggM, stats; also zero aggP for edge3 ---
__global__ void k_node2() {
    const float4* uk4 = reinterpret_cast<const float4*>(g_scratch + 6 * NN);
    const float4* aggVM4 = reinterpret_cast<const float4*>(g_scratch + 2 * NN);
    float2* aggP2z = reinterpret_cast<float2*>(g_scratch + 4 * NN);
    float2* v2 = reinterpret_cast<float2*>(g_scratch + 8 * NN);
    float2* m2 = reinterpret_cast<float2*>(g_scratch + 9 * NN);
    float sv = 0, svv = 0, svk = 0, sm = 0, smm = 0, smk = 0;
    int stride = gridDim.x * blockDim.x;
    const int NH = NN / 2;
    for (int i = blockIdx.x * blockDim.x + threadIdx.x; i < NH; i += stride) {
        float4 ui = uk4[i];
        float4 am = aggVM4[i];
        float v0 = ui.x + am.x, m0 = ui.y + am.y;
        float v1 = ui.z + am.z, m1 = ui.w + am.w;
        v2[i] = make_float2(v0, v1);
        m2[i] = make_float2(m0, m1);
        aggP2z[i] = make_float2(0.f, 0.f);
        sv += v0 + v1; svv += v0 * v0 + v1 * v1; svk += v0 * ui.y + v1 * ui.w;
        sm += m0 + m1; smm += m0 * m0 + m1 * m1; smk += m0 * ui.y + m1 * ui.w;
    }
    float vals[6] = {sv, svv, svk, sm, smm, smk};
    double* dsts[6] = {&g_stats.Sv, &g_stats.Svv, &g_stats.Svk,
                       &g_stats.Sm, &g_stats.Smm, &g_stats.Smk};
    block_red_atomic<6>(vals, dsts);
}

// ---------------- edge pass 3: aggP[d] += v[s] ----------------
__global__ void __launch_bounds__(256, 8) k_edge3(const void* __restrict__ ei) {
    const float* v = g_scratch + 8 * NN;
    float* aggP = g_scratch + 4 * NN;
    const int is32 = g_is32;
    const int4* sp = srcp(ei, is32);
    const int4* dp = dstp(ei, is32);
    const int NQ = EE / 4;
    int stride = gridDim.x * blockDim.x;
    for (int q = blockIdx.x * blockDim.x + threadIdx.x; q < NQ; q += stride) {
        int4 S = __ldg(sp + q);
        int4 D = __ldg(dp + q);
        float v0 = __ldg(v + S.x);
        float v1 = __ldg(v + S.y);
        float v2 = __ldg(v + S.z);
        float v3 = __ldg(v + S.w);
        atomicAdd(&aggP[D.x], v0);
        atomicAdd(&aggP[D.y], v1);
        atomicAdd(&aggP[D.z], v2);
        atomicAdd(&aggP[D.w], v3);
    }
}

// ---------------- node pass 3: p = v + aggP, stats ----------------
__global__ void k_node3() {
    const float2* v2 = reinterpret_cast<const float2*>(g_scratch + 8 * NN);
    const float2* aggP2 = reinterpret_cast<const float2*>(g_scratch + 4 * NN);
    const float4* uk4 = reinterpret_cast<const float4*>(g_scratch + 6 * NN);
    const float2* m2 = reinterpret_cast<const float2*>(g_scratch + 9 * NN);
    float2* p2 = reinterpret_cast<float2*>(g_scratch + 10 * NN);
    float sp = 0, spp = 0, spm = 0, spk = 0;
    int stride = gridDim.x * blockDim.x;
    const int NH = NN / 2;
    for (int i = blockIdx.x * blockDim.x + threadIdx.x; i < NH; i += stride) {
        float2 vv = v2[i];
        float2 ap = aggP2[i];
        float2 mm = m2[i];
        float4 ui = uk4[i];
        float p0 = vv.x + ap.x, p1 = vv.y + ap.y;
        p2[i] = make_float2(p0, p1);
        sp += p0 + p1; spp += p0 * p0 + p1 * p1;
        spm += p0 * mm.x + p1 * mm.y; spk += p0 * ui.y + p1 * ui.w;
    }
    float vals[4] = {sp, spp, spm, spk};
    double* dsts[4] = {&g_stats.Sp, &g_stats.Spp, &g_stats.Spm, &g_stats.Spk};
    block_red_atomic<4>(vals, dsts);
}

// ---------------- coefficient kernel (32 threads, staged shared-memory parallel) --------
__global__ void k_coef(const float* __restrict__ W1a, const float* __restrict__ W1b,
                       const float* __restrict__ W2a, const float* __restrict__ W2b,
                       const float* __restrict__ W3a, const float* __restrict__ W3b,
                       const float* __restrict__ g1, const float* __restrict__ be1,
                       const float* __restrict__ g2, const float* __restrict__ be2,
                       const float* __restrict__ g3, const float* __restrict__ be3,
                       const float* __restrict__ Wf, const float* __restrict__ bf) {
    __shared__ double alpha1[10], z1[10], z2[10], A2[10], B2[10];
    __shared__ double za[10], zb[10], zc[10], A3[10], B3[10], C3[10];
    const int t = threadIdx.x;
    const double Nd = (double)NN;
    double ubar = g_stats.Su / Nd, Vu = g_stats.Suu / Nd - ubar * ubar;
    double vbar = g_stats.Sv / Nd, Vv = g_stats.Svv / Nd - vbar * vbar;
    double kbar = g_stats.Sk / Nd, Vk = g_stats.Skk / Nd - kbar * kbar;
    double pbar = g_stats.Sp / Nd, Vp = g_stats.Spp / Nd - pbar * pbar;
    double mbar = g_stats.Sm / Nd, Vm = g_stats.Smm / Nd - mbar * mbar;
    double Cvk = g_stats.Svk / Nd - vbar * kbar;
    double Cpm = g_stats.Spm / Nd - pbar * mbar;
    double Cpk = g_stats.Spk / Nd - pbar * kbar;
    double Cmk = g_stats.Smk / Nd - mbar * kbar;

    if (t < 10) {
        double w1 = 0;
        for (int j = 0; j < 10; j++) w1 += (double)W1a[j] * (double)W1b[j * 10 + t];
        alpha1[t] = (double)g1[t] * w1 / sqrt(w1 * w1 * Vu + BN_EPS);
    }
    __syncthreads();
    if (t < 10) {
        double s1 = 0, s2 = 0;
        for (int j = 0; j < 10; j++) {
            s1 += alpha1[j] * (double)W2a[j * 10 + t];
            s2 += (double)be1[j] * (double)W2a[j * 10 + t];
        }
        z1[t] = s1; z2[t] = s2;
    }
    __syncthreads();
    if (t < 10) {
        double a2 = 0, e2 = 0;
        for (int j = 0; j < 10; j++) {
            a2 += z1[j] * (double)W2b[j * 10 + t];
            e2 += z2[j] * (double)W2b[j * 10 + t];
        }
        double b2 = e2 - ubar * a2;
        double s = sqrt(a2 * a2 * Vv + b2 * b2 * Vk + 2.0 * a2 * b2 * Cvk + BN_EPS);
        A2[t] = (double)g2[t] * a2 / s;
        B2[t] = (double)g2[t] * b2 / s;
    }
    __syncthreads();
    if (t < 10) {
        double s1 = 0, s2 = 0, s3 = 0;
        for (int j = 0; j < 10; j++) {
            s1 += A2[j] * (double)W3a[j * 10 + t];
            s2 += B2[j] * (double)W3a[j * 10 + t];
            s3 += (double)be2[j] * (double)W3a[j * 10 + t];
        }
        za[t] = s1; zb[t] = s2; zc[t] = s3;
    }
    __syncthreads();
    if (t < 10) {
        double a3 = 0, b3 = 0, e3 = 0;
        for (int j = 0; j < 10; j++) {
            a3 += za[j] * (double)W3b[j * 10 + t];
            b3 += zb[j] * (double)W3b[j * 10 + t];
            e3 += zc[j] * (double)W3b[j * 10 + t];
        }
        double c3 = e3 - vbar * a3 - kbar * b3;
        double s = sqrt(a3 * a3 * Vp + b3 * b3 * Vm + c3 * c3 * Vk +
                        2.0 * a3 * b3 * Cpm + 2.0 * a3 * c3 * Cpk + 2.0 * b3 * c3 * Cmk + BN_EPS);
        A3[t] = (double)g3[t] * a3 / s;
        B3[t] = (double)g3[t] * b3 / s;
        C3[t] = (double)g3[t] * c3 / s;
    }
    __syncthreads();
    if (t < 4) {
        int c = t;
        double lu = 0, lv = 0, lk = 0, lp = 0, lm = 0, l0 = (double)bf[c];
        for (int f = 0; f < 10; f++) {
            double wf1 = (double)Wf[f * 4 + c];
            double wf2 = (double)Wf[(10 + f) * 4 + c];
            double wf3 = (double)Wf[(20 + f) * 4 + c];
            lu += alpha1[f] * wf1;
            lv += A2[f] * wf2;
            lk += B2[f] * wf2 + C3[f] * wf3;
            lp += A3[f] * wf3;
            lm += B3[f] * wf3;
            l0 += (double)be1[f] * wf1 + (double)be2[f] * wf2 + (double)be3[f] * wf3;
        }
        g_coef.Lu[c] = (float)lu; g_coef.Lv[c] = (float)lv; g_coef.Lk[c] = (float)lk;
        g_coef.Lp[c] = (float)lp; g_coef.Lm[c] = (float)lm; g_coef.L0[c] = (float)l0;
        if (c == 0) {
            g_coef.ubar = (float)ubar; g_coef.vbar = (float)vbar; g_coef.kbar = (float)kbar;
            g_coef.pbar = (float)pbar; g_coef.mbar = (float)mbar;
        }
    }
}

// ---------------- node pass 4: softmax -> s (ds folded into edge5) ----------
__global__ void k_node4(float* __restrict__ out) {
    const float4* uk4 = reinterpret_cast<const float4*>(g_scratch + 6 * NN);
    const float2* v2 = reinterpret_cast<const float2*>(g_scratch + 8 * NN);
    const float2* m2 = reinterpret_cast<const float2*>(g_scratch + 9 * NN);
    const float2* p2 = reinterpret_cast<const float2*>(g_scratch + 10 * NN);
    float4* out4 = reinterpret_cast<float4*>(out);
    Coef c = g_coef;
    int stride = gridDim.x * blockDim.x;
    const int NH = NN / 2;
    for (int i = blockIdx.x * blockDim.x + threadIdx.x; i < NH; i += stride) {
        float4 ui = uk4[i];
        float2 vv = v2[i], mm = m2[i], pp = p2[i];
#pragma unroll
        for (int h = 0; h < 2; h++) {
            float du = (h ? ui.z : ui.x) - c.ubar;
            float dk = (h ? ui.w : ui.y) - c.kbar;
            float dv = (h ? vv.y : vv.x) - c.vbar;
            float dm = (h ? mm.y : mm.x) - c.mbar;
            float dp = (h ? pp.y : pp.x) - c.pbar;
            float l0 = du * c.Lu[0] + dv * c.Lv[0] + dk * c.Lk[0] + dp * c.Lp[0] + dm * c.Lm[0] + c.L0[0];
            float l1 = du * c.Lu[1] + dv * c.Lv[1] + dk * c.Lk[1] + dp * c.Lp[1] + dm * c.Lm[1] + c.L0[1];
            float l2 = du * c.Lu[2] + dv * c.Lv[2] + dk * c.Lk[2] + dp * c.Lp[2] + dm * c.Lm[2] + c.L0[2];
            float l3 = du * c.Lu[3] + dv * c.Lv[3] + dk * c.Lk[3] + dp * c.Lp[3] + dm * c.Lm[3] + c.L0[3];
            float mx = fmaxf(fmaxf(l0, l1), fmaxf(l2, l3));
            float e0 = expf(l0 - mx), e1 = expf(l1 - mx), e2 = expf(l2 - mx), e3 = expf(l3 - mx);
            float inv = 1.0f / (e0 + e1 + e2 + e3);
            out4[2 * i + h] = make_float4(e0 * inv, e1 * inv, e2 * inv, e3 * inv);
        }
    }
}

// ------- edge pass 5: pos = sum w_e s[src].s[dst]; ds = sum w_e s[src]; two_m -------
__global__ void __launch_bounds__(256, 8) k_edge5(const void* __restrict__ ei,
                                                  const float* __restrict__ w,
                                                  const float* __restrict__ out) {
    const float4* s4 = reinterpret_cast<const float4*>(out);
    const int is32 = g_is32;
    const int4* sp = srcp(ei, is32);
    const int4* dp = dstp(ei, is32);
    float acc = 0.0f, wsum = 0.0f;
    float d0 = 0, d1 = 0, d2 = 0, d3 = 0;
    const int NQ = EE / 4;
    int stride = gridDim.x * blockDim.x;
    for (int q = blockIdx.x * blockDim.x + threadIdx.x; q < NQ; q += stride) {
        int4 S = __ldg(sp + q);
        int4 D = __ldg(dp + q);
        float4 wv = __ldg(reinterpret_cast<const float4*>(w) + q);
        float4 A0 = __ldg(&s4[S.x]), B0 = __ldg(&s4[D.x]);
        float4 A1 = __ldg(&s4[S.y]), B1 = __ldg(&s4[D.y]);
        float4 A2 = __ldg(&s4[S.z]), B2 = __ldg(&s4[D.z]);
        float4 A3 = __ldg(&s4[S.w]), B3 = __ldg(&s4[D.w]);
        float t0 = wv.x * (A0.x * B0.x + A0.y * B0.y + A0.z * B0.z + A0.w * B0.w);
        float t1 = wv.y * (A1.x * B1.x + A1.y * B1.y + A1.z * B1.z + A1.w * B1.w);
        float t2 = wv.z * (A2.x * B2.x + A2.y * B2.y + A2.z * B2.z + A2.w * B2.w);
        float t3 = wv.w * (A3.x * B3.x + A3.y * B3.y + A3.z * B3.z + A3.w * B3.w);
        acc += (t0 + t1) + (t2 + t3);
        wsum += (wv.x + wv.y) + (wv.z + wv.w);
        d0 += wv.x * A0.x + wv.y * A1.x + wv.z * A2.x + wv.w * A3.x;
        d1 += wv.x * A0.y + wv.y * A1.y + wv.z * A2.y + wv.w * A3.y;
        d2 += wv.x * A0.z + wv.y * A1.z + wv.z * A2.z + wv.w * A3.z;
        d3 += wv.x * A0.w + wv.y * A1.w + wv.z * A2.w + wv.w * A3.w;
    }
    float vals[6] = {acc, wsum, d0, d1, d2, d3};
    double* dsts[6] = {&g_stats.pos, &g_stats.two_m,
                       &g_stats.ds[0], &g_stats.ds[1], &g_stats.ds[2], &g_stats.ds[3]};
    block_red_atomic<6>(vals, dsts);
}

// ---------------- final: q ----------------
__global__ void k_final(float* __restrict__ out) {
    double tm = g_stats.two_m;
    double q = g_stats.pos / tm;
#pragma unroll
    for (int c = 0; c < 4; c++) {
        double d = g_stats.ds[c] / tm;
        q -= d * d;
    }
    out[(size_t)4 * NN] = (float)q;
}

extern "C" void kernel_launch(void* const* d_in, const int* in_sizes, int n_in,
                              void* d_out, int out_size) {
    const float* x = (const float*)d_in[0];
    const void* ei = d_in[1];
    const float* w = (const float*)d_in[2];
    const float* W1a = (const float*)d_in[3];
    const float* W1b = (const float*)d_in[5];
    const float* g1 = (const float*)d_in[7];
    const float* be1 = (const float*)d_in[8];
    const float* W2a = (const float*)d_in[9];
    const float* W2b = (const float*)d_in[11];
    const float* g2 = (const float*)d_in[13];
    const float* be2 = (const float*)d_in[14];
    const float* W3a = (const float*)d_in[15];
    const float* W3b = (const float*)d_in[17];
    const float* g3 = (const float*)d_in[19];
    const float* be3 = (const float*)d_in[20];
    const float* Wf = (const float*)d_in[21];
    const float* bf = (const float*)d_in[22];
    float* out = (float*)d_out;

    const int ET = 256, EB = 1184;   // edge kernels: 8 blocks/SM
    const int NT = 256, NB = 296;    // node kernels: 2 blocks/SM

    k_init<<<NB, NT>>>(ei);
    k_edge1<<<EB, ET>>>(ei, x);
    k_node1<<<NB, NT>>>(x);
    k_edge2<<<EB, ET>>>(ei);
    k_node2<<<NB, NT>>>();
    k_edge3<<<EB, ET>>>(ei);
    k_node3<<<NB, NT>>>();
    k_coef<<<1, 32>>>(W1a, W1b, W2a, W2b, W3a, W3b, g1, be1, g2, be2, g3, be3, Wf, bf);
    k_node4<<<NB, NT>>>(out);
    k_edge5<<<EB, ET>>>(ei, w, out);
    k_final<<<1, 1>>>(out);
}

// round 12
// speedup vs baseline: 1.1267x; 1.1267x over previous
#include <cuda_runtime.h>

#define NN 500000
#define EE 8000000
#define BN_EPS 1e-5

// ---------------- scratch (static device memory; no allocation) ----------------
//  [0:2N)   aggUI  (float2: aggU, indeg)   [zeroed]
//  [2N:4N)  aggVM  (float2: aggV, aggM)    [zeroed]
//  [4N:5N)  aggP                            [zeroed]
//  [6N:8N)  uk     (float2: u, k)
//  [8N:9N)  v
//  [9N:10N) m
//  [10N:11N) p
__device__ float g_scratch[11 * NN];
__device__ int4 g_src[EE / 4];   // packed int32 src (only used when input is int64)
__device__ int4 g_dst[EE / 4];   // packed int32 dst
__device__ int g_is32;

struct Stats {
    double two_m;
    double Su, Suu, Sk, Skk;
    double Sv, Svv, Svk;
    double Sm, Smm, Smk;
    double Sp, Spp, Spm, Spk;
    double pos;
    double ds[4];
};
__device__ Stats g_stats;

struct Coef {
    float Lu[4], Lv[4], Lk[4], Lp[4], Lm[4], L0[4];
    float ubar, vbar, kbar, pbar, mbar;
};
__device__ Coef g_coef;

__device__ __forceinline__ float warp_redf(float v) {
#pragma unroll
    for (int o = 16; o > 0; o >>= 1) v += __shfl_down_sync(0xffffffffu, v, o);
    return v;
}

// Block-level reduction of NV float partials -> ONE double atomic per block per value.
template <int NV>
__device__ __forceinline__ void block_red_atomic(const float* vals, double* const* dsts) {
    __shared__ float sm[NV][8];
    int wid = threadIdx.x >> 5, lid = threadIdx.x & 31;
#pragma unroll
    for (int j = 0; j < NV; j++) {
        float v = warp_redf(vals[j]);
        if (lid == 0) sm[j][wid] = v;
    }
    __syncthreads();
    if (threadIdx.x < NV) {
        float t = 0.0f;
#pragma unroll
        for (int r = 0; r < 8; r++) t += sm[threadIdx.x][r];
        atomicAdd(dsts[threadIdx.x], (double)t);
    }
}

// vector reduction: one 8B atomic add of {a,b} (sm_90+)
__device__ __forceinline__ void red_add_v2(float2* addr, float a, float b) {
    asm volatile("red.global.add.v2.f32 [%0], {%1, %2};"
                 :: "l"(addr), "f"(a), "f"(b) : "memory");
}

__device__ __forceinline__ const int4* srcp(const void* ei, int is32) {
    return is32 ? reinterpret_cast<const int4*>(ei) : g_src;
}
__device__ __forceinline__ const int4* dstp(const void* ei, int is32) {
    return is32 ? reinterpret_cast<const int4*>((const int*)ei + EE) : g_dst;
}

// ---------------- init: zero accumulators + stats, detect index dtype ----------------
__global__ void k_init(const void* ei) {
    int stride = gridDim.x * blockDim.x;
    int tid = blockIdx.x * blockDim.x + threadIdx.x;
    float4* z4 = reinterpret_cast<float4*>(g_scratch);
    const int nz = (5 * NN) / 4;
    for (int i = tid; i < nz; i += stride) z4[i] = make_float4(0.f, 0.f, 0.f, 0.f);
    if (tid < (int)(sizeof(Stats) / sizeof(double))) {
        reinterpret_cast<double*>(&g_stats)[tid] = 0.0;
    }
    if (blockIdx.x == 0) {
        const long long* p = (const long long*)ei;
        int bad = 0;
        for (int i = threadIdx.x; i < 4096; i += blockDim.x) {
            long long v = p[i];
            if (v < 0 || v >= (long long)NN) bad = 1;
        }
        bad = __syncthreads_or(bad);
        if (threadIdx.x == 0) g_is32 = bad;
    }
}

// ------- edge pass 1: aggUI[d] += {x[s],1} (v2 red); pack idx if int64 -------
__global__ void k_edge1(const void* __restrict__ ei,
                        const float* __restrict__ x) {
    float2* aggUI = reinterpret_cast<float2*>(g_scratch);
    const int is32 = g_is32;
    const int NQ = EE / 4;
    int stride = gridDim.x * blockDim.x;
    for (int q = blockIdx.x * blockDim.x + threadIdx.x; q < NQ; q += stride) {
        int4 S, D;
        if (is32) {
            S = __ldg(reinterpret_cast<const int4*>(ei) + q);
            D = __ldg(reinterpret_cast<const int4*>((const int*)ei + EE) + q);
        } else {
            const longlong2* p = reinterpret_cast<const longlong2*>(ei);
            longlong2 a0 = __ldg(p + 2 * q), a1 = __ldg(p + 2 * q + 1);
            longlong2 b0 = __ldg(p + EE / 2 + 2 * q), b1 = __ldg(p + EE / 2 + 2 * q + 1);
            S = make_int4((int)a0.x, (int)a0.y, (int)a1.x, (int)a1.y);
            D = make_int4((int)b0.x, (int)b0.y, (int)b1.x, (int)b1.y);
            g_src[q] = S;
            g_dst[q] = D;
        }
        float xs0 = __ldg(x + S.x);
        float xs1 = __ldg(x + S.y);
        float xs2 = __ldg(x + S.z);
        float xs3 = __ldg(x + S.w);
        red_add_v2(&aggUI[D.x], xs0, 1.0f);
        red_add_v2(&aggUI[D.y], xs1, 1.0f);
        red_add_v2(&aggUI[D.z], xs2, 1.0f);
        red_add_v2(&aggUI[D.w], xs3, 1.0f);
    }
}

// ---------------- node pass 1: u = x + aggU, k = 1 + indeg, stats ----------------
__global__ void k_node1(const float* __restrict__ x) {
    const float4* aggUI4 = reinterpret_cast<const float4*>(g_scratch);
    float4* uk4 = reinterpret_cast<float4*>(g_scratch + 6 * NN);
    const float2* x2 = reinterpret_cast<const float2*>(x);
    float su = 0, suu = 0, sk = 0, skk = 0;
    int stride = gridDim.x * blockDim.x;
    const int NH = NN / 2;
    for (int i = blockIdx.x * blockDim.x + threadIdx.x; i < NH; i += stride) {
        float4 a = aggUI4[i];
        float2 xi = x2[i];
        float u0 = xi.x + a.x, k0 = 1.0f + a.y;
        float u1 = xi.y + a.z, k1 = 1.0f + a.w;
        uk4[i] = make_float4(u0, k0, u1, k1);
        su += u0 + u1; suu += u0 * u0 + u1 * u1;
        sk += k0 + k1; skk += k0 * k0 + k1 * k1;
    }
    float vals[4] = {su, suu, sk, skk};
    double* dsts[4] = {&g_stats.Su, &g_stats.Suu, &g_stats.Sk, &g_stats.Skk};
    block_red_atomic<4>(vals, dsts);
}

// ---------------- edge pass 2: aggVM[d] += uk[s]  (one v2 red) ----------------
__global__ void k_edge2(const void* __restrict__ ei) {
    const float2* uk = reinterpret_cast<const float2*>(g_scratch + 6 * NN);
    float2* aggVM = reinterpret_cast<float2*>(g_scratch + 2 * NN);
    const int is32 = g_is32;
    const int4* sp = srcp(ei, is32);
    const int4* dp = dstp(ei, is32);
    const int NQ = EE / 4;
    int stride = gridDim.x * blockDim.x;
    for (int q = blockIdx.x * blockDim.x + threadIdx.x; q < NQ; q += stride) {
        int4 S = __ldg(sp + q);
        int4 D = __ldg(dp + q);
        float2 u0 = __ldg(&uk[S.x]);
        float2 u1 = __ldg(&uk[S.y]);
        float2 u2 = __ldg(&uk[S.z]);
        float2 u3 = __ldg(&uk[S.w]);
        red_add_v2(&aggVM[D.x], u0.x, u0.y);
        red_add_v2(&aggVM[D.y], u1.x, u1.y);
        red_add_v2(&aggVM[D.z], u2.x, u2.y);
        red_add_v2(&aggVM[D.w], u3.x, u3.y);
    }
}

// ---------------- node pass 2: v = u + aggV, m = k + aggM, stats ----------------
__global__ void k_node2() {
    const float4* uk4 = reinterpret_cast<const float4*>(g_scratch + 6 * NN);
    const float4* aggVM4 = reinterpret_cast<const float4*>(g_scratch + 2 * NN);
    float2* v2 = reinterpret_cast<float2*>(g_scratch + 8 * NN);
    float2* m2 = reinterpret_cast<float2*>(g_scratch + 9 * NN);
    float sv = 0, svv = 0, svk = 0, sm = 0, smm = 0, smk = 0;
    int stride = gridDim.x * blockDim.x;
    const int NH = NN / 2;
    for (int i = blockIdx.x * blockDim.x + threadIdx.x; i < NH; i += stride) {
        float4 ui = uk4[i];
        float4 am = aggVM4[i];
        float v0 = ui.x + am.x, m0 = ui.y + am.y;
        float v1 = ui.z + am.z, m1 = ui.w + am.w;
        v2[i] = make_float2(v0, v1);
        m2[i] = make_float2(m0, m1);
        sv += v0 + v1; svv += v0 * v0 + v1 * v1; svk += v0 * ui.y + v1 * ui.w;
        sm += m0 + m1; smm += m0 * m0 + m1 * m1; smk += m0 * ui.y + m1 * ui.w;
    }
    float vals[6] = {sv, svv, svk, sm, smm, smk};
    double* dsts[6] = {&g_stats.Sv, &g_stats.Svv, &g_stats.Svk,
                       &g_stats.Sm, &g_stats.Smm, &g_stats.Smk};
    block_red_atomic<6>(vals, dsts);
}

// ---------------- edge pass 3: aggP[d] += v[s] ----------------
__global__ void k_edge3(const void* __restrict__ ei) {
    const float* v = g_scratch + 8 * NN;
    float* aggP = g_scratch + 4 * NN;
    const int is32 = g_is32;
    const int4* sp = srcp(ei, is32);
    const int4* dp = dstp(ei, is32);
    const int NQ = EE / 4;
    int stride = gridDim.x * blockDim.x;
    for (int q = blockIdx.x * blockDim.x + threadIdx.x; q < NQ; q += stride) {
        int4 S = __ldg(sp + q);
        int4 D = __ldg(dp + q);
        float v0 = __ldg(v + S.x);
        float v1 = __ldg(v + S.y);
        float v2 = __ldg(v + S.z);
        float v3 = __ldg(v + S.w);
        atomicAdd(&aggP[D.x], v0);
        atomicAdd(&aggP[D.y], v1);
        atomicAdd(&aggP[D.z], v2);
        atomicAdd(&aggP[D.w], v3);
    }
}

// ---------------- node pass 3: p = v + aggP, stats ----------------
__global__ void k_node3() {
    const float2* v2 = reinterpret_cast<const float2*>(g_scratch + 8 * NN);
    const float2* aggP2 = reinterpret_cast<const float2*>(g_scratch + 4 * NN);
    const float4* uk4 = reinterpret_cast<const float4*>(g_scratch + 6 * NN);
    const float2* m2 = reinterpret_cast<const float2*>(g_scratch + 9 * NN);
    float2* p2 = reinterpret_cast<float2*>(g_scratch + 10 * NN);
    float sp = 0, spp = 0, spm = 0, spk = 0;
    int stride = gridDim.x * blockDim.x;
    const int NH = NN / 2;
    for (int i = blockIdx.x * blockDim.x + threadIdx.x; i < NH; i += stride) {
        float2 vv = v2[i];
        float2 ap = aggP2[i];
        float2 mm = m2[i];
        float4 ui = uk4[i];
        float p0 = vv.x + ap.x, p1 = vv.y + ap.y;
        p2[i] = make_float2(p0, p1);
        sp += p0 + p1; spp += p0 * p0 + p1 * p1;
        spm += p0 * mm.x + p1 * mm.y; spk += p0 * ui.y + p1 * ui.w;
    }
    float vals[4] = {sp, spp, spm, spk};
    double* dsts[4] = {&g_stats.Sp, &g_stats.Spp, &g_stats.Spm, &g_stats.Spk};
    block_red_atomic<4>(vals, dsts);
}

// ---------------- coefficient kernel (32 threads, staged shared-memory parallel) --------
__global__ void k_coef(const float* __restrict__ W1a, const float* __restrict__ W1b,
                       const float* __restrict__ W2a, const float* __restrict__ W2b,
                       const float* __restrict__ W3a, const float* __restrict__ W3b,
                       const float* __restrict__ g1, const float* __restrict__ be1,
                       const float* __restrict__ g2, const float* __restrict__ be2,
                       const float* __restrict__ g3, const float* __restrict__ be3,
                       const float* __restrict__ Wf, const float* __restrict__ bf) {
    __shared__ double alpha1[10], z1[10], z2[10], A2[10], B2[10];
    __shared__ double za[10], zb[10], zc[10], A3[10], B3[10], C3[10];
    const int t = threadIdx.x;
    const double Nd = (double)NN;
    double ubar = g_stats.Su / Nd, Vu = g_stats.Suu / Nd - ubar * ubar;
    double vbar = g_stats.Sv / Nd, Vv = g_stats.Svv / Nd - vbar * vbar;
    double kbar = g_stats.Sk / Nd, Vk = g_stats.Skk / Nd - kbar * kbar;
    double pbar = g_stats.Sp / Nd, Vp = g_stats.Spp / Nd - pbar * pbar;
    double mbar = g_stats.Sm / Nd, Vm = g_stats.Smm / Nd - mbar * mbar;
    double Cvk = g_stats.Svk / Nd - vbar * kbar;
    double Cpm = g_stats.Spm / Nd - pbar * mbar;
    double Cpk = g_stats.Spk / Nd - pbar * kbar;
    double Cmk = g_stats.Smk / Nd - mbar * kbar;

    if (t < 10) {
        double w1 = 0;
        for (int j = 0; j < 10; j++) w1 += (double)W1a[j] * (double)W1b[j * 10 + t];
        alpha1[t] = (double)g1[t] * w1 / sqrt(w1 * w1 * Vu + BN_EPS);
    }
    __syncthreads();
    if (t < 10) {
        double s1 = 0, s2 = 0;
        for (int j = 0; j < 10; j++) {
            s1 += alpha1[j] * (double)W2a[j * 10 + t];
            s2 += (double)be1[j] * (double)W2a[j * 10 + t];
        }
        z1[t] = s1; z2[t] = s2;
    }
    __syncthreads();
    if (t < 10) {
        double a2 = 0, e2 = 0;
        for (int j = 0; j < 10; j++) {
            a2 += z1[j] * (double)W2b[j * 10 + t];
            e2 += z2[j] * (double)W2b[j * 10 + t];
        }
        double b2 = e2 - ubar * a2;
        double s = sqrt(a2 * a2 * Vv + b2 * b2 * Vk + 2.0 * a2 * b2 * Cvk + BN_EPS);
        A2[t] = (double)g2[t] * a2 / s;
        B2[t] = (double)g2[t] * b2 / s;
    }
    __syncthreads();
    if (t < 10) {
        double s1 = 0, s2 = 0, s3 = 0;
        for (int j = 0; j < 10; j++) {
            s1 += A2[j] * (double)W3a[j * 10 + t];
            s2 += B2[j] * (double)W3a[j * 10 + t];
            s3 += (double)be2[j] * (double)W3a[j * 10 + t];
        }
        za[t] = s1; zb[t] = s2; zc[t] = s3;
    }
    __syncthreads();
    if (t < 10) {
        double a3 = 0, b3 = 0, e3 = 0;
        for (int j = 0; j < 10; j++) {
            a3 += za[j] * (double)W3b[j * 10 + t];
            b3 += zb[j] * (double)W3b[j * 10 + t];
            e3 += zc[j] * (double)W3b[j * 10 + t];
        }
        double c3 = e3 - vbar * a3 - kbar * b3;
        double s = sqrt(a3 * a3 * Vp + b3 * b3 * Vm + c3 * c3 * Vk +
                        2.0 * a3 * b3 * Cpm + 2.0 * a3 * c3 * Cpk + 2.0 * b3 * c3 * Cmk + BN_EPS);
        A3[t] = (double)g3[t] * a3 / s;
        B3[t] = (double)g3[t] * b3 / s;
        C3[t] = (double)g3[t] * c3 / s;
    }
    __syncthreads();
    if (t < 4) {
        int c = t;
        double lu = 0, lv = 0, lk = 0, lp = 0, lm = 0, l0 = (double)bf[c];
        for (int f = 0; f < 10; f++) {
            double wf1 = (double)Wf[f * 4 + c];
            double wf2 = (double)Wf[(10 + f) * 4 + c];
            double wf3 = (double)Wf[(20 + f) * 4 + c];
            lu += alpha1[f] * wf1;
            lv += A2[f] * wf2;
            lk += B2[f] * wf2 + C3[f] * wf3;
            lp += A3[f] * wf3;
            lm += B3[f] * wf3;
            l0 += (double)be1[f] * wf1 + (double)be2[f] * wf2 + (double)be3[f] * wf3;
        }
        g_coef.Lu[c] = (float)lu; g_coef.Lv[c] = (float)lv; g_coef.Lk[c] = (float)lk;
        g_coef.Lp[c] = (float)lp; g_coef.Lm[c] = (float)lm; g_coef.L0[c] = (float)l0;
        if (c == 0) {
            g_coef.ubar = (float)ubar; g_coef.vbar = (float)vbar; g_coef.kbar = (float)kbar;
            g_coef.pbar = (float)pbar; g_coef.mbar = (float)mbar;
        }
    }
}

// ---------------- node pass 4: softmax -> s (ds folded into edge5) ----------
__global__ void k_node4(float* __restrict__ out) {
    const float4* uk4 = reinterpret_cast<const float4*>(g_scratch + 6 * NN);
    const float2* v2 = reinterpret_cast<const float2*>(g_scratch + 8 * NN);
    const float2* m2 = reinterpret_cast<const float2*>(g_scratch + 9 * NN);
    const float2* p2 = reinterpret_cast<const float2*>(g_scratch + 10 * NN);
    float4* out4 = reinterpret_cast<float4*>(out);
    Coef c = g_coef;
    int stride = gridDim.x * blockDim.x;
    const int NH = NN / 2;
    for (int i = blockIdx.x * blockDim.x + threadIdx.x; i < NH; i += stride) {
        float4 ui = uk4[i];
        float2 vv = v2[i], mm = m2[i], pp = p2[i];
#pragma unroll
        for (int h = 0; h < 2; h++) {
            float du = (h ? ui.z : ui.x) - c.ubar;
            float dk = (h ? ui.w : ui.y) - c.kbar;
            float dv = (h ? vv.y : vv.x) - c.vbar;
            float dm = (h ? mm.y : mm.x) - c.mbar;
            float dp = (h ? pp.y : pp.x) - c.pbar;
            float l0 = du * c.Lu[0] + dv * c.Lv[0] + dk * c.Lk[0] + dp * c.Lp[0] + dm * c.Lm[0] + c.L0[0];
            float l1 = du * c.Lu[1] + dv * c.Lv[1] + dk * c.Lk[1] + dp * c.Lp[1] + dm * c.Lm[1] + c.L0[1];
            float l2 = du * c.Lu[2] + dv * c.Lv[2] + dk * c.Lk[2] + dp * c.Lp[2] + dm * c.Lm[2] + c.L0[2];
            float l3 = du * c.Lu[3] + dv * c.Lv[3] + dk * c.Lk[3] + dp * c.Lp[3] + dm * c.Lm[3] + c.L0[3];
            float mx = fmaxf(fmaxf(l0, l1), fmaxf(l2, l3));
            float e0 = expf(l0 - mx), e1 = expf(l1 - mx), e2 = expf(l2 - mx), e3 = expf(l3 - mx);
            float inv = 1.0f / (e0 + e1 + e2 + e3);
            out4[2 * i + h] = make_float4(e0 * inv, e1 * inv, e2 * inv, e3 * inv);
        }
    }
}

// ------- edge pass 5: pos = sum w_e s[src].s[dst]; ds = sum w_e s[src]; two_m -------
__global__ void k_edge5(const void* __restrict__ ei,
                        const float* __restrict__ w,
                        const float* __restrict__ out) {
    const float4* s4 = reinterpret_cast<const float4*>(out);
    const int is32 = g_is32;
    const int4* sp = srcp(ei, is32);
    const int4* dp = dstp(ei, is32);
    float acc = 0.0f, wsum = 0.0f;
    float d0 = 0, d1 = 0, d2 = 0, d3 = 0;
    const int NQ = EE / 4;
    int stride = gridDim.x * blockDim.x;
    for (int q = blockIdx.x * blockDim.x + threadIdx.x; q < NQ; q += stride) {
        int4 S = __ldg(sp + q);
        int4 D = __ldg(dp + q);
        float4 wv = __ldg(reinterpret_cast<const float4*>(w) + q);
        float4 A0 = __ldg(&s4[S.x]), B0 = __ldg(&s4[D.x]);
        float4 A1 = __ldg(&s4[S.y]), B1 = __ldg(&s4[D.y]);
        float4 A2 = __ldg(&s4[S.z]), B2 = __ldg(&s4[D.z]);
        float4 A3 = __ldg(&s4[S.w]), B3 = __ldg(&s4[D.w]);
        float t0 = wv.x * (A0.x * B0.x + A0.y * B0.y + A0.z * B0.z + A0.w * B0.w);
        float t1 = wv.y * (A1.x * B1.x + A1.y * B1.y + A1.z * B1.z + A1.w * B1.w);
        float t2 = wv.z * (A2.x * B2.x + A2.y * B2.y + A2.z * B2.z + A2.w * B2.w);
        float t3 = wv.w * (A3.x * B3.x + A3.y * B3.y + A3.z * B3.z + A3.w * B3.w);
        acc += (t0 + t1) + (t2 + t3);
        wsum += (wv.x + wv.y) + (wv.z + wv.w);
        d0 += wv.x * A0.x + wv.y * A1.x + wv.z * A2.x + wv.w * A3.x;
        d1 += wv.x * A0.y + wv.y * A1.y + wv.z * A2.y + wv.w * A3.y;
        d2 += wv.x * A0.z + wv.y * A1.z + wv.z * A2.z + wv.w * A3.z;
        d3 += wv.x * A0.w + wv.y * A1.w + wv.z * A2.w + wv.w * A3.w;
    }
    float vals[6] = {acc, wsum, d0, d1, d2, d3};
    double* dsts[6] = {&g_stats.pos, &g_stats.two_m,
                       &g_stats.ds[0], &g_stats.ds[1], &g_stats.ds[2], &g_stats.ds[3]};
    block_red_atomic<6>(vals, dsts);
}

// ---------------- final: q ----------------
__global__ void k_final(float* __restrict__ out) {
    double tm = g_stats.two_m;
    double q = g_stats.pos / tm;
#pragma unroll
    for (int c = 0; c < 4; c++) {
        double d = g_stats.ds[c] / tm;
        q -= d * d;
    }
    out[(size_t)4 * NN] = (float)q;
}

extern "C" void kernel_launch(void* const* d_in, const int* in_sizes, int n_in,
                              void* d_out, int out_size) {
    const float* x = (const float*)d_in[0];
    const void* ei = d_in[1];
    const float* w = (const float*)d_in[2];
    const float* W1a = (const float*)d_in[3];
    const float* W1b = (const float*)d_in[5];
    const float* g1 = (const float*)d_in[7];
    const float* be1 = (const float*)d_in[8];
    const float* W2a = (const float*)d_in[9];
    const float* W2b = (const float*)d_in[11];
    const float* g2 = (const float*)d_in[13];
    const float* be2 = (const float*)d_in[14];
    const float* W3a = (const float*)d_in[15];
    const float* W3b = (const float*)d_in[17];
    const float* g3 = (const float*)d_in[19];
    const float* be3 = (const float*)d_in[20];
    const float* Wf = (const float*)d_in[21];
    const float* bf = (const float*)d_in[22];
    float* out = (float*)d_out;

    const int ET = 256, EB = 1184;   // edge kernels: 8 blocks/SM
    const int NT = 256, NB = 296;    // node kernels: 2 blocks/SM

    k_init<<<NB, NT>>>(ei);
    k_edge1<<<EB, ET>>>(ei, x);
    k_node1<<<NB, NT>>>(x);
    k_edge2<<<EB, ET>>>(ei);
    k_node2<<<NB, NT>>>();
    k_edge3<<<EB, ET>>>(ei);
    k_node3<<<NB, NT>>>();
    k_coef<<<1, 32>>>(W1a, W1b, W2a, W2b, W3a, W3b, g1, be1, g2, be2, g3, be3, Wf, bf);
    k_node4<<<NB, NT>>>(out);
    k_edge5<<<EB, ET>>>(ei, w, out);
    k_final<<<1, 1>>>(out);
}

// round 13
// speedup vs baseline: 1.1346x; 1.0070x over previous
#include <cuda_runtime.h>

#define NN 500000
#define EE 8000000
#define BN_EPS 1e-5

// ---------------- scratch (static device memory; no allocation) ----------------
//  [0:2N)   aggUI  (float2: aggU, indeg)   [zeroed]
//  [2N:4N)  aggVM  (float2: aggV, aggM)    [zeroed]
//  [4N:5N)  aggP                            [zeroed]
//  [6N:8N)  uk     (float2: u, k)
//  [8N:9N)  v
//  [9N:10N) m
//  [10N:11N) p
__device__ float g_scratch[11 * NN];
__device__ int4 g_src[EE / 4];   // packed int32 src (only used when input is int64)
__device__ int4 g_dst[EE / 4];   // packed int32 dst
__device__ int g_is32;

struct Stats {
    double two_m;
    double Su, Suu, Sk, Skk;
    double Sv, Svv, Svk;
    double Sm, Smm, Smk;
    double Sp, Spp, Spm, Spk;
    double pos;
    double ds[4];
};
__device__ Stats g_stats;

struct Coef {
    float Lu[4], Lv[4], Lk[4], Lp[4], Lm[4], L0[4];
    float ubar, vbar, kbar, pbar, mbar;
};
__device__ Coef g_coef;

__device__ __forceinline__ float warp_redf(float v) {
#pragma unroll
    for (int o = 16; o > 0; o >>= 1) v += __shfl_down_sync(0xffffffffu, v, o);
    return v;
}

// Block-level reduction of NV float partials -> ONE double atomic per block per value.
template <int NV>
__device__ __forceinline__ void block_red_atomic(const float* vals, double* const* dsts) {
    __shared__ float sm[NV][8];
    int wid = threadIdx.x >> 5, lid = threadIdx.x & 31;
#pragma unroll
    for (int j = 0; j < NV; j++) {
        float v = warp_redf(vals[j]);
        if (lid == 0) sm[j][wid] = v;
    }
    __syncthreads();
    if (threadIdx.x < NV) {
        float t = 0.0f;
#pragma unroll
        for (int r = 0; r < 8; r++) t += sm[threadIdx.x][r];
        atomicAdd(dsts[threadIdx.x], (double)t);
    }
}

// vector reduction: one 8B atomic add of {a,b} (sm_90+)
__device__ __forceinline__ void red_add_v2(float2* addr, float a, float b) {
    asm volatile("red.global.add.v2.f32 [%0], {%1, %2};"
                 :: "l"(addr), "f"(a), "f"(b) : "memory");
}

__device__ __forceinline__ const int4* srcp(const void* ei, int is32) {
    return is32 ? reinterpret_cast<const int4*>(ei) : g_src;
}
__device__ __forceinline__ const int4* dstp(const void* ei, int is32) {
    return is32 ? reinterpret_cast<const int4*>((const int*)ei + EE) : g_dst;
}

// ---------------- init: zero accumulators + stats, detect index dtype ----------------
__global__ void k_init(const void* ei) {
    int stride = gridDim.x * blockDim.x;
    int tid = blockIdx.x * blockDim.x + threadIdx.x;
    float4* z4 = reinterpret_cast<float4*>(g_scratch);
    const int nz = (5 * NN) / 4;
    for (int i = tid; i < nz; i += stride) z4[i] = make_float4(0.f, 0.f, 0.f, 0.f);
    if (tid < (int)(sizeof(Stats) / sizeof(double))) {
        reinterpret_cast<double*>(&g_stats)[tid] = 0.0;
    }
    if (blockIdx.x == 0) {
        const long long* p = (const long long*)ei;
        int bad = 0;
        for (int i = threadIdx.x; i < 4096; i += blockDim.x) {
            long long v = p[i];
            if (v < 0 || v >= (long long)NN) bad = 1;
        }
        bad = __syncthreads_or(bad);
        if (threadIdx.x == 0) g_is32 = bad;
    }
}

// ------- edge pass 1: aggUI[d] += {x[s],1} (v2 red); pack idx if int64 -------
__global__ void k_edge1(const void* __restrict__ ei,
                        const float* __restrict__ x) {
    float2* aggUI = reinterpret_cast<float2*>(g_scratch);
    const int is32 = g_is32;
    const int NQ = EE / 4;
    int stride = gridDim.x * blockDim.x;
    for (int q = blockIdx.x * blockDim.x + threadIdx.x; q < NQ; q += stride) {
        int4 S, D;
        if (is32) {
            S = __ldg(reinterpret_cast<const int4*>(ei) + q);
            D = __ldg(reinterpret_cast<const int4*>((const int*)ei + EE) + q);
        } else {
            const longlong2* p = reinterpret_cast<const longlong2*>(ei);
            longlong2 a0 = __ldg(p + 2 * q), a1 = __ldg(p + 2 * q + 1);
            longlong2 b0 = __ldg(p + EE / 2 + 2 * q), b1 = __ldg(p + EE / 2 + 2 * q + 1);
            S = make_int4((int)a0.x, (int)a0.y, (int)a1.x, (int)a1.y);
            D = make_int4((int)b0.x, (int)b0.y, (int)b1.x, (int)b1.y);
            g_src[q] = S;
            g_dst[q] = D;
        }
        float xs0 = __ldg(x + S.x);
        float xs1 = __ldg(x + S.y);
        float xs2 = __ldg(x + S.z);
        float xs3 = __ldg(x + S.w);
        red_add_v2(&aggUI[D.x], xs0, 1.0f);
        red_add_v2(&aggUI[D.y], xs1, 1.0f);
        red_add_v2(&aggUI[D.z], xs2, 1.0f);
        red_add_v2(&aggUI[D.w], xs3, 1.0f);
    }
}

// ---------------- node pass 1: u = x + aggU, k = 1 + indeg, stats ----------------
__global__ void k_node1(const float* __restrict__ x) {
    const float4* aggUI4 = reinterpret_cast<const float4*>(g_scratch);
    float4* uk4 = reinterpret_cast<float4*>(g_scratch + 6 * NN);
    const float2* x2 = reinterpret_cast<const float2*>(x);
    float su = 0, suu = 0, sk = 0, skk = 0;
    int stride = gridDim.x * blockDim.x;
    const int NH = NN / 2;
    for (int i = blockIdx.x * blockDim.x + threadIdx.x; i < NH; i += stride) {
        float4 a = aggUI4[i];
        float2 xi = x2[i];
        float u0 = xi.x + a.x, k0 = 1.0f + a.y;
        float u1 = xi.y + a.z, k1 = 1.0f + a.w;
        uk4[i] = make_float4(u0, k0, u1, k1);
        su += u0 + u1; suu += u0 * u0 + u1 * u1;
        sk += k0 + k1; skk += k0 * k0 + k1 * k1;
    }
    float vals[4] = {su, suu, sk, skk};
    double* dsts[4] = {&g_stats.Su, &g_stats.Suu, &g_stats.Sk, &g_stats.Skk};
    block_red_atomic<4>(vals, dsts);
}

// ---------------- edge pass 2: aggVM[d] += uk[s]  (one v2 red) ----------------
__global__ void k_edge2(const void* __restrict__ ei) {
    const float2* uk = reinterpret_cast<const float2*>(g_scratch + 6 * NN);
    float2* aggVM = reinterpret_cast<float2*>(g_scratch + 2 * NN);
    const int is32 = g_is32;
    const int4* sp = srcp(ei, is32);
    const int4* dp = dstp(ei, is32);
    const int NQ = EE / 4;
    int stride = gridDim.x * blockDim.x;
    for (int q = blockIdx.x * blockDim.x + threadIdx.x; q < NQ; q += stride) {
        int4 S = __ldg(sp + q);
        int4 D = __ldg(dp + q);
        float2 u0 = __ldg(&uk[S.x]);
        float2 u1 = __ldg(&uk[S.y]);
        float2 u2 = __ldg(&uk[S.z]);
        float2 u3 = __ldg(&uk[S.w]);
        red_add_v2(&aggVM[D.x], u0.x, u0.y);
        red_add_v2(&aggVM[D.y], u1.x, u1.y);
        red_add_v2(&aggVM[D.z], u2.x, u2.y);
        red_add_v2(&aggVM[D.w], u3.x, u3.y);
    }
}

// ---------------- node pass 2: v = u + aggV, m = k + aggM, stats ----------------
__global__ void k_node2() {
    const float4* uk4 = reinterpret_cast<const float4*>(g_scratch + 6 * NN);
    const float4* aggVM4 = reinterpret_cast<const float4*>(g_scratch + 2 * NN);
    float2* v2 = reinterpret_cast<float2*>(g_scratch + 8 * NN);
    float2* m2 = reinterpret_cast<float2*>(g_scratch + 9 * NN);
    float sv = 0, svv = 0, svk = 0, sm = 0, smm = 0, smk = 0;
    int stride = gridDim.x * blockDim.x;
    const int NH = NN / 2;
    for (int i = blockIdx.x * blockDim.x + threadIdx.x; i < NH; i += stride) {
        float4 ui = uk4[i];
        float4 am = aggVM4[i];
        float v0 = ui.x + am.x, m0 = ui.y + am.y;
        float v1 = ui.z + am.z, m1 = ui.w + am.w;
        v2[i] = make_float2(v0, v1);
        m2[i] = make_float2(m0, m1);
        sv += v0 + v1; svv += v0 * v0 + v1 * v1; svk += v0 * ui.y + v1 * ui.w;
        sm += m0 + m1; smm += m0 * m0 + m1 * m1; smk += m0 * ui.y + m1 * ui.w;
    }
    float vals[6] = {sv, svv, svk, sm, smm, smk};
    double* dsts[6] = {&g_stats.Sv, &g_stats.Svv, &g_stats.Svk,
                       &g_stats.Sm, &g_stats.Smm, &g_stats.Smk};
    block_red_atomic<6>(vals, dsts);
}

// ---------------- edge pass 3: aggP[d] += v[s] ----------------
__global__ void k_edge3(const void* __restrict__ ei) {
    const float* v = g_scratch + 8 * NN;
    float* aggP = g_scratch + 4 * NN;
    const int is32 = g_is32;
    const int4* sp = srcp(ei, is32);
    const int4* dp = dstp(ei, is32);
    const int NQ = EE / 4;
    int stride = gridDim.x * blockDim.x;
    for (int q = blockIdx.x * blockDim.x + threadIdx.x; q < NQ; q += stride) {
        int4 S = __ldg(sp + q);
        int4 D = __ldg(dp + q);
        float v0 = __ldg(v + S.x);
        float v1 = __ldg(v + S.y);
        float v2 = __ldg(v + S.z);
        float v3 = __ldg(v + S.w);
        atomicAdd(&aggP[D.x], v0);
        atomicAdd(&aggP[D.y], v1);
        atomicAdd(&aggP[D.z], v2);
        atomicAdd(&aggP[D.w], v3);
    }
}

// ---------------- node pass 3: p = v + aggP, stats ----------------
__global__ void k_node3() {
    const float2* v2 = reinterpret_cast<const float2*>(g_scratch + 8 * NN);
    const float2* aggP2 = reinterpret_cast<const float2*>(g_scratch + 4 * NN);
    const float4* uk4 = reinterpret_cast<const float4*>(g_scratch + 6 * NN);
    const float2* m2 = reinterpret_cast<const float2*>(g_scratch + 9 * NN);
    float2* p2 = reinterpret_cast<float2*>(g_scratch + 10 * NN);
    float sp = 0, spp = 0, spm = 0, spk = 0;
    int stride = gridDim.x * blockDim.x;
    const int NH = NN / 2;
    for (int i = blockIdx.x * blockDim.x + threadIdx.x; i < NH; i += stride) {
        float2 vv = v2[i];
        float2 ap = aggP2[i];
        float2 mm = m2[i];
        float4 ui = uk4[i];
        float p0 = vv.x + ap.x, p1 = vv.y + ap.y;
        p2[i] = make_float2(p0, p1);
        sp += p0 + p1; spp += p0 * p0 + p1 * p1;
        spm += p0 * mm.x + p1 * mm.y; spk += p0 * ui.y + p1 * ui.w;
    }
    float vals[4] = {sp, spp, spm, spk};
    double* dsts[4] = {&g_stats.Sp, &g_stats.Spp, &g_stats.Spm, &g_stats.Spk};
    block_red_atomic<4>(vals, dsts);
}

// ---------------- coefficient kernel (32 threads, staged shared-memory parallel) --------
__global__ void k_coef(const float* __restrict__ W1a, const float* __restrict__ W1b,
                       const float* __restrict__ W2a, const float* __restrict__ W2b,
                       const float* __restrict__ W3a, const float* __restrict__ W3b,
                       const float* __restrict__ g1, const float* __restrict__ be1,
                       const float* __restrict__ g2, const float* __restrict__ be2,
                       const float* __restrict__ g3, const float* __restrict__ be3,
                       const float* __restrict__ Wf, const float* __restrict__ bf) {
    __shared__ double alpha1[10], z1[10], z2[10], A2[10], B2[10];
    __shared__ double za[10], zb[10], zc[10], A3[10], B3[10], C3[10];
    const int t = threadIdx.x;
    const double Nd = (double)NN;
    double ubar = g_stats.Su / Nd, Vu = g_stats.Suu / Nd - ubar * ubar;
    double vbar = g_stats.Sv / Nd, Vv = g_stats.Svv / Nd - vbar * vbar;
    double kbar = g_stats.Sk / Nd, Vk = g_stats.Skk / Nd - kbar * kbar;
    double pbar = g_stats.Sp / Nd, Vp = g_stats.Spp / Nd - pbar * pbar;
    double mbar = g_stats.Sm / Nd, Vm = g_stats.Smm / Nd - mbar * mbar;
    double Cvk = g_stats.Svk / Nd - vbar * kbar;
    double Cpm = g_stats.Spm / Nd - pbar * mbar;
    double Cpk = g_stats.Spk / Nd - pbar * kbar;
    double Cmk = g_stats.Smk / Nd - mbar * kbar;

    if (t < 10) {
        double w1 = 0;
        for (int j = 0; j < 10; j++) w1 += (double)W1a[j] * (double)W1b[j * 10 + t];
        alpha1[t] = (double)g1[t] * w1 / sqrt(w1 * w1 * Vu + BN_EPS);
    }
    __syncthreads();
    if (t < 10) {
        double s1 = 0, s2 = 0;
        for (int j = 0; j < 10; j++) {
            s1 += alpha1[j] * (double)W2a[j * 10 + t];
            s2 += (double)be1[j] * (double)W2a[j * 10 + t];
        }
        z1[t] = s1; z2[t] = s2;
    }
    __syncthreads();
    if (t < 10) {
        double a2 = 0, e2 = 0;
        for (int j = 0; j < 10; j++) {
            a2 += z1[j] * (double)W2b[j * 10 + t];
            e2 += z2[j] * (double)W2b[j * 10 + t];
        }
        double b2 = e2 - ubar * a2;
        double s = sqrt(a2 * a2 * Vv + b2 * b2 * Vk + 2.0 * a2 * b2 * Cvk + BN_EPS);
        A2[t] = (double)g2[t] * a2 / s;
        B2[t] = (double)g2[t] * b2 / s;
    }
    __syncthreads();
    if (t < 10) {
        double s1 = 0, s2 = 0, s3 = 0;
        for (int j = 0; j < 10; j++) {
            s1 += A2[j] * (double)W3a[j * 10 + t];
            s2 += B2[j] * (double)W3a[j * 10 + t];
            s3 += (double)be2[j] * (double)W3a[j * 10 + t];
        }
        za[t] = s1; zb[t] = s2; zc[t] = s3;
    }
    __syncthreads();
    if (t < 10) {
        double a3 = 0, b3 = 0, e3 = 0;
        for (int j = 0; j < 10; j++) {
            a3 += za[j] * (double)W3b[j * 10 + t];
            b3 += zb[j] * (double)W3b[j * 10 + t];
            e3 += zc[j] * (double)W3b[j * 10 + t];
        }
        double c3 = e3 - vbar * a3 - kbar * b3;
        double s = sqrt(a3 * a3 * Vp + b3 * b3 * Vm + c3 * c3 * Vk +
                        2.0 * a3 * b3 * Cpm + 2.0 * a3 * c3 * Cpk + 2.0 * b3 * c3 * Cmk + BN_EPS);
        A3[t] = (double)g3[t] * a3 / s;
        B3[t] = (double)g3[t] * b3 / s;
        C3[t] = (double)g3[t] * c3 / s;
    }
    __syncthreads();
    if (t < 4) {
        int c = t;
        double lu = 0, lv = 0, lk = 0, lp = 0, lm = 0, l0 = (double)bf[c];
        for (int f = 0; f < 10; f++) {
            double wf1 = (double)Wf[f * 4 + c];
            double wf2 = (double)Wf[(10 + f) * 4 + c];
            double wf3 = (double)Wf[(20 + f) * 4 + c];
            lu += alpha1[f] * wf1;
            lv += A2[f] * wf2;
            lk += B2[f] * wf2 + C3[f] * wf3;
            lp += A3[f] * wf3;
            lm += B3[f] * wf3;
            l0 += (double)be1[f] * wf1 + (double)be2[f] * wf2 + (double)be3[f] * wf3;
        }
        g_coef.Lu[c] = (float)lu; g_coef.Lv[c] = (float)lv; g_coef.Lk[c] = (float)lk;
        g_coef.Lp[c] = (float)lp; g_coef.Lm[c] = (float)lm; g_coef.L0[c] = (float)l0;
        if (c == 0) {
            g_coef.ubar = (float)ubar; g_coef.vbar = (float)vbar; g_coef.kbar = (float)kbar;
            g_coef.pbar = (float)pbar; g_coef.mbar = (float)mbar;
        }
    }
}

// ---------------- node pass 4: softmax -> s (ds folded into edge5) ----------
__global__ void k_node4(float* __restrict__ out) {
    const float4* uk4 = reinterpret_cast<const float4*>(g_scratch + 6 * NN);
    const float2* v2 = reinterpret_cast<const float2*>(g_scratch + 8 * NN);
    const float2* m2 = reinterpret_cast<const float2*>(g_scratch + 9 * NN);
    const float2* p2 = reinterpret_cast<const float2*>(g_scratch + 10 * NN);
    float4* out4 = reinterpret_cast<float4*>(out);
    Coef c = g_coef;
    int stride = gridDim.x * blockDim.x;
    const int NH = NN / 2;
    for (int i = blockIdx.x * blockDim.x + threadIdx.x; i < NH; i += stride) {
        float4 ui = uk4[i];
        float2 vv = v2[i], mm = m2[i], pp = p2[i];
#pragma unroll
        for (int h = 0; h < 2; h++) {
            float du = (h ? ui.z : ui.x) - c.ubar;
            float dk = (h ? ui.w : ui.y) - c.kbar;
            float dv = (h ? vv.y : vv.x) - c.vbar;
            float dm = (h ? mm.y : mm.x) - c.mbar;
            float dp = (h ? pp.y : pp.x) - c.pbar;
            float l0 = du * c.Lu[0] + dv * c.Lv[0] + dk * c.Lk[0] + dp * c.Lp[0] + dm * c.Lm[0] + c.L0[0];
            float l1 = du * c.Lu[1] + dv * c.Lv[1] + dk * c.Lk[1] + dp * c.Lp[1] + dm * c.Lm[1] + c.L0[1];
            float l2 = du * c.Lu[2] + dv * c.Lv[2] + dk * c.Lk[2] + dp * c.Lp[2] + dm * c.Lm[2] + c.L0[2];
            float l3 = du * c.Lu[3] + dv * c.Lv[3] + dk * c.Lk[3] + dp * c.Lp[3] + dm * c.Lm[3] + c.L0[3];
            float mx = fmaxf(fmaxf(l0, l1), fmaxf(l2, l3));
            float e0 = expf(l0 - mx), e1 = expf(l1 - mx), e2 = expf(l2 - mx), e3 = expf(l3 - mx);
            float inv = 1.0f / (e0 + e1 + e2 + e3);
            out4[2 * i + h] = make_float4(e0 * inv, e1 * inv, e2 * inv, e3 * inv);
        }
    }
}

// ------- edge pass 5: pos = sum w_e s[src].s[dst]; ds = sum w_e s[src]; two_m -------
__global__ void k_edge5(const void* __restrict__ ei,
                        const float* __restrict__ w,
                        const float* __restrict__ out) {
    const float4* s4 = reinterpret_cast<const float4*>(out);
    const int is32 = g_is32;
    const int4* sp = srcp(ei, is32);
    const int4* dp = dstp(ei, is32);
    float acc = 0.0f, wsum = 0.0f;
    float d0 = 0, d1 = 0, d2 = 0, d3 = 0;
    const int NQ = EE / 4;
    int stride = gridDim.x * blockDim.x;
    for (int q = blockIdx.x * blockDim.x + threadIdx.x; q < NQ; q += stride) {
        int4 S = __ldg(sp + q);
        int4 D = __ldg(dp + q);
        float4 wv = __ldg(reinterpret_cast<const float4*>(w) + q);
        float4 A0 = __ldg(&s4[S.x]), B0 = __ldg(&s4[D.x]);
        float4 A1 = __ldg(&s4[S.y]), B1 = __ldg(&s4[D.y]);
        float4 A2 = __ldg(&s4[S.z]), B2 = __ldg(&s4[D.z]);
        float4 A3 = __ldg(&s4[S.w]), B3 = __ldg(&s4[D.w]);
        float t0 = wv.x * (A0.x * B0.x + A0.y * B0.y + A0.z * B0.z + A0.w * B0.w);
        float t1 = wv.y * (A1.x * B1.x + A1.y * B1.y + A1.z * B1.z + A1.w * B1.w);
        float t2 = wv.z * (A2.x * B2.x + A2.y * B2.y + A2.z * B2.z + A2.w * B2.w);
        float t3 = wv.w * (A3.x * B3.x + A3.y * B3.y + A3.z * B3.z + A3.w * B3.w);
        acc += (t0 + t1) + (t2 + t3);
        wsum += (wv.x + wv.y) + (wv.z + wv.w);
        d0 += wv.x * A0.x + wv.y * A1.x + wv.z * A2.x + wv.w * A3.x;
        d1 += wv.x * A0.y + wv.y * A1.y + wv.z * A2.y + wv.w * A3.y;
        d2 += wv.x * A0.z + wv.y * A1.z + wv.z * A2.z + wv.w * A3.z;
        d3 += wv.x * A0.w + wv.y * A1.w + wv.z * A2.w + wv.w * A3.w;
    }
    float vals[6] = {acc, wsum, d0, d1, d2, d3};
    double* dsts[6] = {&g_stats.pos, &g_stats.two_m,
                       &g_stats.ds[0], &g_stats.ds[1], &g_stats.ds[2], &g_stats.ds[3]};
    block_red_atomic<6>(vals, dsts);
}

// ---------------- final: q ----------------
__global__ void k_final(float* __restrict__ out) {
    double tm = g_stats.two_m;
    double q = g_stats.pos / tm;
#pragma unroll
    for (int c = 0; c < 4; c++) {
        double d = g_stats.ds[c] / tm;
        q -= d * d;
    }
    out[(size_t)4 * NN] = (float)q;
}

extern "C" void kernel_launch(void* const* d_in, const int* in_sizes, int n_in,
                              void* d_out, int out_size) {
    const float* x = (const float*)d_in[0];
    const void* ei = d_in[1];
    const float* w = (const float*)d_in[2];
    const float* W1a = (const float*)d_in[3];
    const float* W1b = (const float*)d_in[5];
    const float* g1 = (const float*)d_in[7];
    const float* be1 = (const float*)d_in[8];
    const float* W2a = (const float*)d_in[9];
    const float* W2b = (const float*)d_in[11];
    const float* g2 = (const float*)d_in[13];
    const float* be2 = (const float*)d_in[14];
    const float* W3a = (const float*)d_in[15];
    const float* W3b = (const float*)d_in[17];
    const float* g3 = (const float*)d_in[19];
    const float* be3 = (const float*)d_in[20];
    const float* Wf = (const float*)d_in[21];
    const float* bf = (const float*)d_in[22];
    float* out = (float*)d_out;

    const int ET = 256, EB = 2368;   // edge kernels: 2 waves of 8 blocks/SM (tail rebalancing)
    const int NT = 256, NB = 296;    // node kernels: 2 blocks/SM

    k_init<<<NB, NT>>>(ei);
    k_edge1<<<EB, ET>>>(ei, x);
    k_node1<<<NB, NT>>>(x);
    k_edge2<<<EB, ET>>>(ei);
    k_node2<<<NB, NT>>>();
    k_edge3<<<EB, ET>>>(ei);
    k_node3<<<NB, NT>>>();
    k_coef<<<1, 32>>>(W1a, W1b, W2a, W2b, W3a, W3b, g1, be1, g2, be2, g3, be3, Wf, bf);
    k_node4<<<NB, NT>>>(out);
    k_edge5<<<EB, ET>>>(ei, w, out);
    k_final<<<1, 1>>>(out);
}

// round 14
// speedup vs baseline: 1.1647x; 1.0265x over previous
#include <cuda_runtime.h>

#define NN 500000
#define EE 8000000
#define BN_EPS 1e-5

// ---------------- scratch (static device memory; no allocation) ----------------
//  [0:2N)   aggUI  (float2: aggU, indeg)   [zeroed]
//  [2N:4N)  aggVM  (float2: aggV, aggM)    [zeroed]
//  [4N:5N)  aggP                            [zeroed]
//  [6N:8N)  uk     (float2: u, k)
//  [8N:9N)  v
//  [9N:10N) m
//  [10N:11N) p
__device__ float g_scratch[11 * NN];
__device__ int4 g_src[EE / 4];   // packed int32 src (only used when input is int64)
__device__ int4 g_dst[EE / 4];   // packed int32 dst
__device__ int g_is32;

struct Stats {
    double two_m;
    double Su, Suu, Sk, Skk;
    double Sv, Svv, Svk;
    double Sm, Smm, Smk;
    double Sp, Spp, Spm, Spk;
    double pos;
    double ds[4];
};
__device__ Stats g_stats;

struct Coef {
    float Lu[4], Lv[4], Lk[4], Lp[4], Lm[4], L0[4];
    float ubar, vbar, kbar, pbar, mbar;
};
__device__ Coef g_coef;

__device__ __forceinline__ float warp_redf(float v) {
#pragma unroll
    for (int o = 16; o > 0; o >>= 1) v += __shfl_down_sync(0xffffffffu, v, o);
    return v;
}

// Block-level reduction of NV float partials -> ONE double atomic per block per value.
template <int NV>
__device__ __forceinline__ void block_red_atomic(const float* vals, double* const* dsts) {
    __shared__ float sm[NV][8];
    int wid = threadIdx.x >> 5, lid = threadIdx.x & 31;
#pragma unroll
    for (int j = 0; j < NV; j++) {
        float v = warp_redf(vals[j]);
        if (lid == 0) sm[j][wid] = v;
    }
    __syncthreads();
    if (threadIdx.x < NV) {
        float t = 0.0f;
#pragma unroll
        for (int r = 0; r < 8; r++) t += sm[threadIdx.x][r];
        atomicAdd(dsts[threadIdx.x], (double)t);
    }
}

// vector reduction: one 8B atomic add of {a,b} (sm_90+)
__device__ __forceinline__ void red_add_v2(float2* addr, float a, float b) {
    asm volatile("red.global.add.v2.f32 [%0], {%1, %2};"
                 :: "l"(addr), "f"(a), "f"(b) : "memory");
}

__device__ __forceinline__ const int4* srcp(const void* ei, int is32) {
    return is32 ? reinterpret_cast<const int4*>(ei) : g_src;
}
__device__ __forceinline__ const int4* dstp(const void* ei, int is32) {
    return is32 ? reinterpret_cast<const int4*>((const int*)ei + EE) : g_dst;
}

// ---------------- init: zero accumulators + stats, detect index dtype ----------------
__global__ void k_init(const void* ei) {
    int stride = gridDim.x * blockDim.x;
    int tid = blockIdx.x * blockDim.x + threadIdx.x;
    float4* z4 = reinterpret_cast<float4*>(g_scratch);
    const int nz = (5 * NN) / 4;
    for (int i = tid; i < nz; i += stride) z4[i] = make_float4(0.f, 0.f, 0.f, 0.f);
    if (tid < (int)(sizeof(Stats) / sizeof(double))) {
        reinterpret_cast<double*>(&g_stats)[tid] = 0.0;
    }
    if (blockIdx.x == 0) {
        const long long* p = (const long long*)ei;
        int bad = 0;
        for (int i = threadIdx.x; i < 4096; i += blockDim.x) {
            long long v = p[i];
            if (v < 0 || v >= (long long)NN) bad = 1;
        }
        bad = __syncthreads_or(bad);
        if (threadIdx.x == 0) g_is32 = bad;
    }
}

// ------- edge pass 1: aggUI[d] += {x[s],1} (v2 red); pack idx if int64 -------
__global__ void k_edge1(const void* __restrict__ ei,
                        const float* __restrict__ x) {
    float2* aggUI = reinterpret_cast<float2*>(g_scratch);
    const int is32 = g_is32;
    const int NQ = EE / 4;
    int stride = gridDim.x * blockDim.x;
    for (int q = blockIdx.x * blockDim.x + threadIdx.x; q < NQ; q += stride) {
        int4 S, D;
        if (is32) {
            S = __ldg(reinterpret_cast<const int4*>(ei) + q);
            D = __ldg(reinterpret_cast<const int4*>((const int*)ei + EE) + q);
        } else {
            const longlong2* p = reinterpret_cast<const longlong2*>(ei);
            longlong2 a0 = __ldg(p + 2 * q), a1 = __ldg(p + 2 * q + 1);
            longlong2 b0 = __ldg(p + EE / 2 + 2 * q), b1 = __ldg(p + EE / 2 + 2 * q + 1);
            S = make_int4((int)a0.x, (int)a0.y, (int)a1.x, (int)a1.y);
            D = make_int4((int)b0.x, (int)b0.y, (int)b1.x, (int)b1.y);
            g_src[q] = S;
            g_dst[q] = D;
        }
        float xs0 = __ldg(x + S.x);
        float xs1 = __ldg(x + S.y);
        float xs2 = __ldg(x + S.z);
        float xs3 = __ldg(x + S.w);
        red_add_v2(&aggUI[D.x], xs0, 1.0f);
        red_add_v2(&aggUI[D.y], xs1, 1.0f);
        red_add_v2(&aggUI[D.z], xs2, 1.0f);
        red_add_v2(&aggUI[D.w], xs3, 1.0f);
    }
}

// ---------------- node pass 1: u = x + aggU, k = 1 + indeg, stats ----------------
__global__ void k_node1(const float* __restrict__ x) {
    const float4* aggUI4 = reinterpret_cast<const float4*>(g_scratch);
    float4* uk4 = reinterpret_cast<float4*>(g_scratch + 6 * NN);
    const float2* x2 = reinterpret_cast<const float2*>(x);
    float su = 0, suu = 0, sk = 0, skk = 0;
    int stride = gridDim.x * blockDim.x;
    const int NH = NN / 2;
    for (int i = blockIdx.x * blockDim.x + threadIdx.x; i < NH; i += stride) {
        float4 a = aggUI4[i];
        float2 xi = x2[i];
        float u0 = xi.x + a.x, k0 = 1.0f + a.y;
        float u1 = xi.y + a.z, k1 = 1.0f + a.w;
        uk4[i] = make_float4(u0, k0, u1, k1);
        su += u0 + u1; suu += u0 * u0 + u1 * u1;
        sk += k0 + k1; skk += k0 * k0 + k1 * k1;
    }
    float vals[4] = {su, suu, sk, skk};
    double* dsts[4] = {&g_stats.Su, &g_stats.Suu, &g_stats.Sk, &g_stats.Skk};
    block_red_atomic<4>(vals, dsts);
}

// ---------------- edge pass 2: aggVM[d] += uk[s]  (one v2 red) ----------------
__global__ void k_edge2(const void* __restrict__ ei) {
    const float2* uk = reinterpret_cast<const float2*>(g_scratch + 6 * NN);
    float2* aggVM = reinterpret_cast<float2*>(g_scratch + 2 * NN);
    const int is32 = g_is32;
    const int4* sp = srcp(ei, is32);
    const int4* dp = dstp(ei, is32);
    const int NQ = EE / 4;
    int stride = gridDim.x * blockDim.x;
    for (int q = blockIdx.x * blockDim.x + threadIdx.x; q < NQ; q += stride) {
        int4 S = __ldg(sp + q);
        int4 D = __ldg(dp + q);
        float2 u0 = __ldg(&uk[S.x]);
        float2 u1 = __ldg(&uk[S.y]);
        float2 u2 = __ldg(&uk[S.z]);
        float2 u3 = __ldg(&uk[S.w]);
        red_add_v2(&aggVM[D.x], u0.x, u0.y);
        red_add_v2(&aggVM[D.y], u1.x, u1.y);
        red_add_v2(&aggVM[D.z], u2.x, u2.y);
        red_add_v2(&aggVM[D.w], u3.x, u3.y);
    }
}

// ---------------- node pass 2: v = u + aggV, m = k + aggM, stats ----------------
__global__ void k_node2() {
    const float4* uk4 = reinterpret_cast<const float4*>(g_scratch + 6 * NN);
    const float4* aggVM4 = reinterpret_cast<const float4*>(g_scratch + 2 * NN);
    float2* v2 = reinterpret_cast<float2*>(g_scratch + 8 * NN);
    float2* m2 = reinterpret_cast<float2*>(g_scratch + 9 * NN);
    float sv = 0, svv = 0, svk = 0, sm = 0, smm = 0, smk = 0;
    int stride = gridDim.x * blockDim.x;
    const int NH = NN / 2;
    for (int i = blockIdx.x * blockDim.x + threadIdx.x; i < NH; i += stride) {
        float4 ui = uk4[i];
        float4 am = aggVM4[i];
        float v0 = ui.x + am.x, m0 = ui.y + am.y;
        float v1 = ui.z + am.z, m1 = ui.w + am.w;
        v2[i] = make_float2(v0, v1);
        m2[i] = make_float2(m0, m1);
        sv += v0 + v1; svv += v0 * v0 + v1 * v1; svk += v0 * ui.y + v1 * ui.w;
        sm += m0 + m1; smm += m0 * m0 + m1 * m1; smk += m0 * ui.y + m1 * ui.w;
    }
    float vals[6] = {sv, svv, svk, sm, smm, smk};
    double* dsts[6] = {&g_stats.Sv, &g_stats.Svv, &g_stats.Svk,
                       &g_stats.Sm, &g_stats.Smm, &g_stats.Smk};
    block_red_atomic<6>(vals, dsts);
}

// ---------------- edge pass 3: aggP[d] += v[s] ----------------
__global__ void k_edge3(const void* __restrict__ ei) {
    const float* v = g_scratch + 8 * NN;
    float* aggP = g_scratch + 4 * NN;
    const int is32 = g_is32;
    const int4* sp = srcp(ei, is32);
    const int4* dp = dstp(ei, is32);
    const int NQ = EE / 4;
    int stride = gridDim.x * blockDim.x;
    for (int q = blockIdx.x * blockDim.x + threadIdx.x; q < NQ; q += stride) {
        int4 S = __ldg(sp + q);
        int4 D = __ldg(dp + q);
        float v0 = __ldg(v + S.x);
        float v1 = __ldg(v + S.y);
        float v2 = __ldg(v + S.z);
        float v3 = __ldg(v + S.w);
        atomicAdd(&aggP[D.x], v0);
        atomicAdd(&aggP[D.y], v1);
        atomicAdd(&aggP[D.z], v2);
        atomicAdd(&aggP[D.w], v3);
    }
}

// ---------------- node pass 3: p = v + aggP, stats ----------------
__global__ void k_node3() {
    const float2* v2 = reinterpret_cast<const float2*>(g_scratch + 8 * NN);
    const float2* aggP2 = reinterpret_cast<const float2*>(g_scratch + 4 * NN);
    const float4* uk4 = reinterpret_cast<const float4*>(g_scratch + 6 * NN);
    const float2* m2 = reinterpret_cast<const float2*>(g_scratch + 9 * NN);
    float2* p2 = reinterpret_cast<float2*>(g_scratch + 10 * NN);
    float sp = 0, spp = 0, spm = 0, spk = 0;
    int stride = gridDim.x * blockDim.x;
    const int NH = NN / 2;
    for (int i = blockIdx.x * blockDim.x + threadIdx.x; i < NH; i += stride) {
        float2 vv = v2[i];
        float2 ap = aggP2[i];
        float2 mm = m2[i];
        float4 ui = uk4[i];
        float p0 = vv.x + ap.x, p1 = vv.y + ap.y;
        p2[i] = make_float2(p0, p1);
        sp += p0 + p1; spp += p0 * p0 + p1 * p1;
        spm += p0 * mm.x + p1 * mm.y; spk += p0 * ui.y + p1 * ui.w;
    }
    float vals[4] = {sp, spp, spm, spk};
    double* dsts[4] = {&g_stats.Sp, &g_stats.Spp, &g_stats.Spm, &g_stats.Spk};
    block_red_atomic<4>(vals, dsts);
}

// ---------------- coefficient kernel (32 threads, staged shared-memory parallel) --------
__global__ void k_coef(const float* __restrict__ W1a, const float* __restrict__ W1b,
                       const float* __restrict__ W2a, const float* __restrict__ W2b,
                       const float* __restrict__ W3a, const float* __restrict__ W3b,
                       const float* __restrict__ g1, const float* __restrict__ be1,
                       const float* __restrict__ g2, const float* __restrict__ be2,
                       const float* __restrict__ g3, const float* __restrict__ be3,
                       const float* __restrict__ Wf, const float* __restrict__ bf) {
    __shared__ double alpha1[10], z1[10], z2[10], A2[10], B2[10];
    __shared__ double za[10], zb[10], zc[10], A3[10], B3[10], C3[10];
    const int t = threadIdx.x;
    const double Nd = (double)NN;
    double ubar = g_stats.Su / Nd, Vu = g_stats.Suu / Nd - ubar * ubar;
    double vbar = g_stats.Sv / Nd, Vv = g_stats.Svv / Nd - vbar * vbar;
    double kbar = g_stats.Sk / Nd, Vk = g_stats.Skk / Nd - kbar * kbar;
    double pbar = g_stats.Sp / Nd, Vp = g_stats.Spp / Nd - pbar * pbar;
    double mbar = g_stats.Sm / Nd, Vm = g_stats.Smm / Nd - mbar * mbar;
    double Cvk = g_stats.Svk / Nd - vbar * kbar;
    double Cpm = g_stats.Spm / Nd - pbar * mbar;
    double Cpk = g_stats.Spk / Nd - pbar * kbar;
    double Cmk = g_stats.Smk / Nd - mbar * kbar;

    if (t < 10) {
        double w1 = 0;
        for (int j = 0; j < 10; j++) w1 += (double)W1a[j] * (double)W1b[j * 10 + t];
        alpha1[t] = (double)g1[t] * w1 / sqrt(w1 * w1 * Vu + BN_EPS);
    }
    __syncthreads();
    if (t < 10) {
        double s1 = 0, s2 = 0;
        for (int j = 0; j < 10; j++) {
            s1 += alpha1[j] * (double)W2a[j * 10 + t];
            s2 += (double)be1[j] * (double)W2a[j * 10 + t];
        }
        z1[t] = s1; z2[t] = s2;
    }
    __syncthreads();
    if (t < 10) {
        double a2 = 0, e2 = 0;
        for (int j = 0; j < 10; j++) {
            a2 += z1[j] * (double)W2b[j * 10 + t];
            e2 += z2[j] * (double)W2b[j * 10 + t];
        }
        double b2 = e2 - ubar * a2;
        double s = sqrt(a2 * a2 * Vv + b2 * b2 * Vk + 2.0 * a2 * b2 * Cvk + BN_EPS);
        A2[t] = (double)g2[t] * a2 / s;
        B2[t] = (double)g2[t] * b2 / s;
    }
    __syncthreads();
    if (t < 10) {
        double s1 = 0, s2 = 0, s3 = 0;
        for (int j = 0; j < 10; j++) {
            s1 += A2[j] * (double)W3a[j * 10 + t];
            s2 += B2[j] * (double)W3a[j * 10 + t];
            s3 += (double)be2[j] * (double)W3a[j * 10 + t];
        }
        za[t] = s1; zb[t] = s2; zc[t] = s3;
    }
    __syncthreads();
    if (t < 10) {
        double a3 = 0, b3 = 0, e3 = 0;
        for (int j = 0; j < 10; j++) {
            a3 += za[j] * (double)W3b[j * 10 + t];
            b3 += zb[j] * (double)W3b[j * 10 + t];
            e3 += zc[j] * (double)W3b[j * 10 + t];
        }
        double c3 = e3 - vbar * a3 - kbar * b3;
        double s = sqrt(a3 * a3 * Vp + b3 * b3 * Vm + c3 * c3 * Vk +
                        2.0 * a3 * b3 * Cpm + 2.0 * a3 * c3 * Cpk + 2.0 * b3 * c3 * Cmk + BN_EPS);
        A3[t] = (double)g3[t] * a3 / s;
        B3[t] = (double)g3[t] * b3 / s;
        C3[t] = (double)g3[t] * c3 / s;
    }
    __syncthreads();
    if (t < 4) {
        int c = t;
        double lu = 0, lv = 0, lk = 0, lp = 0, lm = 0, l0 = (double)bf[c];
        for (int f = 0; f < 10; f++) {
            double wf1 = (double)Wf[f * 4 + c];
            double wf2 = (double)Wf[(10 + f) * 4 + c];
            double wf3 = (double)Wf[(20 + f) * 4 + c];
            lu += alpha1[f] * wf1;
            lv += A2[f] * wf2;
            lk += B2[f] * wf2 + C3[f] * wf3;
            lp += A3[f] * wf3;
            lm += B3[f] * wf3;
            l0 += (double)be1[f] * wf1 + (double)be2[f] * wf2 + (double)be3[f] * wf3;
        }
        g_coef.Lu[c] = (float)lu; g_coef.Lv[c] = (float)lv; g_coef.Lk[c] = (float)lk;
        g_coef.Lp[c] = (float)lp; g_coef.Lm[c] = (float)lm; g_coef.L0[c] = (float)l0;
        if (c == 0) {
            g_coef.ubar = (float)ubar; g_coef.vbar = (float)vbar; g_coef.kbar = (float)kbar;
            g_coef.pbar = (float)pbar; g_coef.mbar = (float)mbar;
        }
    }
}

// ---------------- node pass 4: softmax -> s (ds folded into edge5) ----------
__global__ void k_node4(float* __restrict__ out) {
    const float4* uk4 = reinterpret_cast<const float4*>(g_scratch + 6 * NN);
    const float2* v2 = reinterpret_cast<const float2*>(g_scratch + 8 * NN);
    const float2* m2 = reinterpret_cast<const float2*>(g_scratch + 9 * NN);
    const float2* p2 = reinterpret_cast<const float2*>(g_scratch + 10 * NN);
    float4* out4 = reinterpret_cast<float4*>(out);
    Coef c = g_coef;
    int stride = gridDim.x * blockDim.x;
    const int NH = NN / 2;
    for (int i = blockIdx.x * blockDim.x + threadIdx.x; i < NH; i += stride) {
        float4 ui = uk4[i];
        float2 vv = v2[i], mm = m2[i], pp = p2[i];
#pragma unroll
        for (int h = 0; h < 2; h++) {
            float du = (h ? ui.z : ui.x) - c.ubar;
            float dk = (h ? ui.w : ui.y) - c.kbar;
            float dv = (h ? vv.y : vv.x) - c.vbar;
            float dm = (h ? mm.y : mm.x) - c.mbar;
            float dp = (h ? pp.y : pp.x) - c.pbar;
            float l0 = du * c.Lu[0] + dv * c.Lv[0] + dk * c.Lk[0] + dp * c.Lp[0] + dm * c.Lm[0] + c.L0[0];
            float l1 = du * c.Lu[1] + dv * c.Lv[1] + dk * c.Lk[1] + dp * c.Lp[1] + dm * c.Lm[1] + c.L0[1];
            float l2 = du * c.Lu[2] + dv * c.Lv[2] + dk * c.Lk[2] + dp * c.Lp[2] + dm * c.Lm[2] + c.L0[2];
            float l3 = du * c.Lu[3] + dv * c.Lv[3] + dk * c.Lk[3] + dp * c.Lp[3] + dm * c.Lm[3] + c.L0[3];
            float mx = fmaxf(fmaxf(l0, l1), fmaxf(l2, l3));
            float e0 = expf(l0 - mx), e1 = expf(l1 - mx), e2 = expf(l2 - mx), e3 = expf(l3 - mx);
            float inv = 1.0f / (e0 + e1 + e2 + e3);
            out4[2 * i + h] = make_float4(e0 * inv, e1 * inv, e2 * inv, e3 * inv);
        }
    }
}

// ------- edge pass 5: pos = sum w_e s[src].s[dst]; ds = sum w_e s[src]; two_m -------
__global__ void k_edge5(const void* __restrict__ ei,
                        const float* __restrict__ w,
                        const float* __restrict__ out) {
    const float4* s4 = reinterpret_cast<const float4*>(out);
    const int is32 = g_is32;
    const int4* sp = srcp(ei, is32);
    const int4* dp = dstp(ei, is32);
    float acc = 0.0f, wsum = 0.0f;
    float d0 = 0, d1 = 0, d2 = 0, d3 = 0;
    const int NQ = EE / 4;
    int stride = gridDim.x * blockDim.x;
    for (int q = blockIdx.x * blockDim.x + threadIdx.x; q < NQ; q += stride) {
        int4 S = __ldg(sp + q);
        int4 D = __ldg(dp + q);
        float4 wv = __ldg(reinterpret_cast<const float4*>(w) + q);
        float4 A0 = __ldg(&s4[S.x]), B0 = __ldg(&s4[D.x]);
        float4 A1 = __ldg(&s4[S.y]), B1 = __ldg(&s4[D.y]);
        float4 A2 = __ldg(&s4[S.z]), B2 = __ldg(&s4[D.z]);
        float4 A3 = __ldg(&s4[S.w]), B3 = __ldg(&s4[D.w]);
        float t0 = wv.x * (A0.x * B0.x + A0.y * B0.y + A0.z * B0.z + A0.w * B0.w);
        float t1 = wv.y * (A1.x * B1.x + A1.y * B1.y + A1.z * B1.z + A1.w * B1.w);
        float t2 = wv.z * (A2.x * B2.x + A2.y * B2.y + A2.z * B2.z + A2.w * B2.w);
        float t3 = wv.w * (A3.x * B3.x + A3.y * B3.y + A3.z * B3.z + A3.w * B3.w);
        acc += (t0 + t1) + (t2 + t3);
        wsum += (wv.x + wv.y) + (wv.z + wv.w);
        d0 += wv.x * A0.x + wv.y * A1.x + wv.z * A2.x + wv.w * A3.x;
        d1 += wv.x * A0.y + wv.y * A1.y + wv.z * A2.y + wv.w * A3.y;
        d2 += wv.x * A0.z + wv.y * A1.z + wv.z * A2.z + wv.w * A3.z;
        d3 += wv.x * A0.w + wv.y * A1.w + wv.z * A2.w + wv.w * A3.w;
    }
    float vals[6] = {acc, wsum, d0, d1, d2, d3};
    double* dsts[6] = {&g_stats.pos, &g_stats.two_m,
                       &g_stats.ds[0], &g_stats.ds[1], &g_stats.ds[2], &g_stats.ds[3]};
    block_red_atomic<6>(vals, dsts);
}

// ---------------- final: q ----------------
__global__ void k_final(float* __restrict__ out) {
    double tm = g_stats.two_m;
    double q = g_stats.pos / tm;
#pragma unroll
    for (int c = 0; c < 4; c++) {
        double d = g_stats.ds[c] / tm;
        q -= d * d;
    }
    out[(size_t)4 * NN] = (float)q;
}

extern "C" void kernel_launch(void* const* d_in, const int* in_sizes, int n_in,
                              void* d_out, int out_size) {
    const float* x = (const float*)d_in[0];
    const void* ei = d_in[1];
    const float* w = (const float*)d_in[2];
    const float* W1a = (const float*)d_in[3];
    const float* W1b = (const float*)d_in[5];
    const float* g1 = (const float*)d_in[7];
    const float* be1 = (const float*)d_in[8];
    const float* W2a = (const float*)d_in[9];
    const float* W2b = (const float*)d_in[11];
    const float* g2 = (const float*)d_in[13];
    const float* be2 = (const float*)d_in[14];
    const float* W3a = (const float*)d_in[15];
    const float* W3b = (const float*)d_in[17];
    const float* g3 = (const float*)d_in[19];
    const float* be3 = (const float*)d_in[20];
    const float* Wf = (const float*)d_in[21];
    const float* bf = (const float*)d_in[22];
    float* out = (float*)d_out;

    const int ET = 256, EB = 4736;   // edge kernels: 4 waves of 8 blocks/SM (finer tail rebalancing)
    const int NT = 256, NB = 296;    // node kernels: 2 blocks/SM

    k_init<<<NB, NT>>>(ei);
    k_edge1<<<EB, ET>>>(ei, x);
    k_node1<<<NB, NT>>>(x);
    k_edge2<<<EB, ET>>>(ei);
    k_node2<<<NB, NT>>>();
    k_edge3<<<EB, ET>>>(ei);
    k_node3<<<NB, NT>>>();
    k_coef<<<1, 32>>>(W1a, W1b, W2a, W2b, W3a, W3b, g1, be1, g2, be2, g3, be3, Wf, bf);
    k_node4<<<NB, NT>>>(out);
    k_edge5<<<EB, ET>>>(ei, w, out);
    k_final<<<1, 1>>>(out);
}